// round 3
// baseline (speedup 1.0000x reference)
#include <cuda_runtime.h>

// RandomShiftsAug: x (128,9,224,224) f32, shift (128,1,1,2) i32 in [0, 2*pad].
// Equivalent to bilinear grid_sample of the replicate-padded (232x232) image at
// an (almost exactly integer) per-image shift. Coordinates are separable:
// x-params depend on (n, j) only, y-params on (n, i) only.

#define N_IMG 128
#define C_CH  9
#define H_IMG 224
#define W_IMG 224
#define PADV  4
#define HP    (H_IMG + 2 * PADV)      // 232 (== WP; H==W)
#define ROWS_PB 16
#define TILES_PER_CH (H_IMG / ROWS_PB) // 14

__global__ __launch_bounds__(224) void shift_aug_kernel(
    const float* __restrict__ x,
    const int*   __restrict__ shift,
    float*       __restrict__ out)
{
    __shared__ int   s_xc0[W_IMG];
    __shared__ int   s_xc1[W_IMG];
    __shared__ float s_xw0[W_IMG];
    __shared__ float s_xw1[W_IMG];
    __shared__ int   s_yc0[ROWS_PB];
    __shared__ int   s_yc1[ROWS_PB];
    __shared__ float s_yw0[ROWS_PB];
    __shared__ float s_yw1[ROWS_PB];

    const int blk  = blockIdx.x;
    const int tile = blk % TILES_PER_CH;
    const int tmp  = blk / TILES_PER_CH;
    const int c    = tmp % C_CH;
    const int n    = tmp / C_CH;
    const int j    = threadIdx.x;   // 0..223

    // Faithful fp32 coordinate math (same for both axes since H==W).
    const float eps   = 1.0f / (float)HP;
    const float start = -1.0f + eps;
    const float stop  =  1.0f - eps;
    const float step  = (stop - start) / (float)(HP - 1);
    const float scale = eps + eps;   // 1/H2 + 1/W2

    // --- x-axis params for column j (shift[..., 0] is the width shift) ---
    {
        float sxf   = (float)shift[2 * n + 0];
        float a     = start + (float)j * step;
        float g     = a + sxf * scale;
        float coord = ((g + 1.0f) * (float)HP - 1.0f) * 0.5f;
        float f0    = floorf(coord);
        int   i0    = (int)f0;
        int   i1    = i0 + 1;
        float w1    = coord - f0;
        float w0    = 1.0f - w1;
        // fold zero-padding validity into the weight; clamp maps padded->orig (replicate)
        s_xw0[j] = (i0 >= 0 && i0 <= HP - 1) ? w0 : 0.0f;
        s_xw1[j] = (i1 >= 0 && i1 <= HP - 1) ? w1 : 0.0f;
        s_xc0[j] = min(max(i0 - PADV, 0), W_IMG - 1);
        s_xc1[j] = min(max(i1 - PADV, 0), W_IMG - 1);
    }
    // --- y-axis params for the 16 rows of this tile (shift[..., 1] is height) ---
    if (j < ROWS_PB) {
        int   i     = tile * ROWS_PB + j;
        float syf   = (float)shift[2 * n + 1];
        float a     = start + (float)i * step;
        float g     = a + syf * scale;
        float coord = ((g + 1.0f) * (float)HP - 1.0f) * 0.5f;
        float f0    = floorf(coord);
        int   i0    = (int)f0;
        int   i1    = i0 + 1;
        float w1    = coord - f0;
        float w0    = 1.0f - w1;
        s_yw0[j] = (i0 >= 0 && i0 <= HP - 1) ? w0 : 0.0f;
        s_yw1[j] = (i1 >= 0 && i1 <= HP - 1) ? w1 : 0.0f;
        s_yc0[j] = min(max(i0 - PADV, 0), H_IMG - 1);
        s_yc1[j] = min(max(i1 - PADV, 0), H_IMG - 1);
    }
    __syncthreads();

    // Hoist per-column params into registers (constant over the 16-row loop).
    const int   xc0 = s_xc0[j];
    const int   xc1 = s_xc1[j];
    const float xw0 = s_xw0[j];
    const float xw1 = s_xw1[j];

    const float* img    = x   + (size_t)(n * C_CH + c) * (H_IMG * W_IMG);
    float*       outptr = out + (size_t)(n * C_CH + c) * (H_IMG * W_IMG)
                              + (size_t)(tile * ROWS_PB) * W_IMG + j;

    #pragma unroll 4
    for (int r = 0; r < ROWS_PB; ++r) {
        const float* row0 = img + s_yc0[r] * W_IMG;
        const float* row1 = img + s_yc1[r] * W_IMG;
        float v00 = row0[xc0];
        float v01 = row0[xc1];
        float v10 = row1[xc0];
        float v11 = row1[xc1];
        float top = v00 * xw0 + v01 * xw1;
        float bot = v10 * xw0 + v11 * xw1;
        outptr[r * W_IMG] = top * s_yw0[r] + bot * s_yw1[r];
    }
}

extern "C" void kernel_launch(void* const* d_in, const int* in_sizes, int n_in,
                              void* d_out, int out_size) {
    const float* x     = (const float*)d_in[0];
    const int*   shift = (const int*)d_in[1];
    float*       out   = (float*)d_out;
    shift_aug_kernel<<<N_IMG * C_CH * TILES_PER_CH, 224>>>(x, shift, out);
}

// round 4
// speedup vs baseline: 1.2556x; 1.2556x over previous
#include <cuda_runtime.h>

// RandomShiftsAug: x (128,9,224,224) f32, shift (128,1,1,2) i32 in [0, 2*pad].
// coord = pixel_index + shift_raw exactly (math), so this is a near-integer
// shifted copy on the replicate-padded 232x232 canvas, with zero-padding
// validity folded into bilinear weights.
//
// Design: per block = one (n,c) x 16 output rows.
//   Phase A: stage 18 x-blended input rows into smem (faithful per-column
//            bilinear x-weights held in registers; y-clamp folded into which
//            gmem row each smem row stages).
//   Phase B: vector y-blend: 2x LDS.128 + FFMA + STG.128 per 4 pixels.

#define N_IMG 128
#define C_CH  9
#define H_IMG 224
#define W_IMG 224
#define PADV  4
#define HP    (H_IMG + 2 * PADV)        // 232 (== WP since H==W)
#define ROWS_PB 16
#define STAGE_ROWS (ROWS_PB + 2)        // 18: covers floor-jitter +/-1 and y1
#define TILES_PER_CH (H_IMG / ROWS_PB)  // 14
#define SM_STRIDE 228                   // multiple of 4 (float4), 228%32=4

__global__ __launch_bounds__(224) void shift_aug_kernel(
    const float* __restrict__ x,
    const int*   __restrict__ shift,
    float*       __restrict__ out)
{
    __shared__ float s_rows[STAGE_ROWS * SM_STRIDE];
    __shared__ int   s_yidx[ROWS_PB];
    __shared__ float s_yw0[ROWS_PB];
    __shared__ float s_yw1[ROWS_PB];

    const int blk  = blockIdx.x;
    const int tile = blk % TILES_PER_CH;
    const int tmp  = blk / TILES_PER_CH;
    const int c    = tmp % C_CH;
    const int n    = tmp / C_CH;
    const int j    = threadIdx.x;           // 0..223
    const int T    = tile * ROWS_PB;        // first output row of this tile

    // Faithful fp32 coordinate constants (same both axes, H==W).
    const float eps   = 1.0f / (float)HP;
    const float start = -1.0f + eps;
    const float stop  =  1.0f - eps;
    const float step  = (stop - start) / (float)(HP - 1);
    const float scale = eps + eps;          // 1/H2 + 1/W2

    const int sx_raw = shift[2 * n + 0];
    const int sy_raw = shift[2 * n + 1];
    // First staged (unclamped) input row. coord_y(i) == i + sy_raw exactly in
    // math; fp jitter moves floor by at most -1, so rows [T+sy_raw-5, +17]
    // cover every y0/y1 this tile can touch.
    const int S0 = T + sy_raw - 5;

    // --- per-thread x params (column j), kept in registers ---
    float xw0, xw1;
    int   xc0, xc1;
    {
        float a     = start + (float)j * step;
        float g     = a + (float)sx_raw * scale;
        float coord = ((g + 1.0f) * (float)HP - 1.0f) * 0.5f;
        float f0    = floorf(coord);
        int   i0p   = (int)f0;              // padded-canvas coord
        float w1    = coord - f0;
        float w0    = 1.0f - w1;
        xw0 = (i0p >= 0     && i0p     <= HP - 1) ? w0 : 0.0f;
        xw1 = (i0p + 1 >= 0 && i0p + 1 <= HP - 1) ? w1 : 0.0f;
        xc0 = min(max(i0p     - PADV, 0), W_IMG - 1);
        xc1 = min(max(i0p + 1 - PADV, 0), W_IMG - 1);
    }

    // --- y params for the 16 output rows of this tile ---
    if (j < ROWS_PB) {
        int   i     = T + j;
        float a     = start + (float)i * step;
        float g     = a + (float)sy_raw * scale;
        float coord = ((g + 1.0f) * (float)HP - 1.0f) * 0.5f;
        float f0    = floorf(coord);
        int   i0p   = (int)f0;
        float w1    = coord - f0;
        float w0    = 1.0f - w1;
        s_yw0[j]  = (i0p >= 0     && i0p     <= HP - 1) ? w0 : 0.0f;
        s_yw1[j]  = (i0p + 1 >= 0 && i0p + 1 <= HP - 1) ? w1 : 0.0f;
        s_yidx[j] = (i0p - PADV) - S0;      // in [0, 16]; +1 gives y1 row
    }

    // --- Phase A: stage 18 x-blended rows ---
    const float* img = x + (size_t)(n * C_CH + c) * (H_IMG * W_IMG);
    #pragma unroll
    for (int k = 0; k < STAGE_ROWS; ++k) {
        int src = min(max(S0 + k, 0), H_IMG - 1);   // y replicate-clamp here
        const float* row = img + src * W_IMG;
        s_rows[k * SM_STRIDE + j] = row[xc0] * xw0 + row[xc1] * xw1;
    }
    __syncthreads();

    // --- Phase B: vector y-blend, float4 out ---
    const int c4   = j % 56;                 // float4 column 0..55
    const int rsub = j / 56;                 // 0..3
    float* outbase = out + (size_t)(n * C_CH + c) * (H_IMG * W_IMG);

    #pragma unroll
    for (int p = 0; p < 4; ++p) {
        int   r  = p * 4 + rsub;             // 0..15
        int   yi = s_yidx[r];
        float w0 = s_yw0[r];
        float w1 = s_yw1[r];
        const float4 a = *(const float4*)&s_rows[ yi      * SM_STRIDE + 4 * c4];
        const float4 b = *(const float4*)&s_rows[(yi + 1) * SM_STRIDE + 4 * c4];
        float4 o;
        o.x = a.x * w0 + b.x * w1;
        o.y = a.y * w0 + b.y * w1;
        o.z = a.z * w0 + b.z * w1;
        o.w = a.w * w0 + b.w * w1;
        *(float4*)&outbase[(size_t)(T + r) * W_IMG + 4 * c4] = o;
    }
}

extern "C" void kernel_launch(void* const* d_in, const int* in_sizes, int n_in,
                              void* d_out, int out_size) {
    const float* x     = (const float*)d_in[0];
    const int*   shift = (const int*)d_in[1];
    float*       out   = (float*)d_out;
    shift_aug_kernel<<<N_IMG * C_CH * TILES_PER_CH, 224>>>(x, shift, out);
}

// round 5
// speedup vs baseline: 1.3287x; 1.0582x over previous
#include <cuda_runtime.h>

// RandomShiftsAug: x (128,9,224,224) f32, shift (128,1,1,2) i32 in [0, 2*pad].
// Near-integer shifted copy on the replicate-padded 232x232 canvas; bilinear
// weights are faithful fp32 (zero-padding validity folded into weights).
//
// Per block: one (n,c) x 8 output rows.
//  A1: stage 10 raw rows into smem, aligned coalesced LDG.128 only.
//  A2: x-blend from smem (conflict-free LDS.32), per-column params in regs.
//  B : vector y-blend, LDS.128 x2 + STG.128 per 4 pixels.

#define N_IMG 128
#define C_CH  9
#define H_IMG 224
#define W_IMG 224
#define PADV  4
#define HP    (H_IMG + 2 * PADV)        // 232 (== WP since H==W)
#define ROWS_PB 8
#define STAGE_ROWS (ROWS_PB + 2)        // 10: covers fp floor-jitter and y1
#define TILES_PER_CH (H_IMG / ROWS_PB)  // 28
#define RAW_STRIDE 224                  // floats; 16B-aligned rows
#define BL_STRIDE  228                  // floats; mult of 4, rotates banks
#define F4_PER_ROW (W_IMG / 4)          // 56
#define STAGE_F4   (STAGE_ROWS * F4_PER_ROW)  // 560

__global__ __launch_bounds__(224, 8) void shift_aug_kernel(
    const float* __restrict__ x,
    const int*   __restrict__ shift,
    float*       __restrict__ out)
{
    __shared__ float s_raw  [STAGE_ROWS * RAW_STRIDE];
    __shared__ float s_blend[STAGE_ROWS * BL_STRIDE];
    __shared__ int   s_yidx[ROWS_PB];
    __shared__ float s_yw0[ROWS_PB];
    __shared__ float s_yw1[ROWS_PB];

    const int blk  = blockIdx.x;
    const int tile = blk % TILES_PER_CH;
    const int tmp  = blk / TILES_PER_CH;
    const int c    = tmp % C_CH;
    const int n    = tmp / C_CH;
    const int j    = threadIdx.x;           // 0..223
    const int T    = tile * ROWS_PB;        // first output row of tile

    // Faithful fp32 coordinate constants (same both axes, H==W).
    const float eps   = 1.0f / (float)HP;
    const float start = -1.0f + eps;
    const float stop  =  1.0f - eps;
    const float step  = (stop - start) / (float)(HP - 1);
    const float scale = eps + eps;          // 1/H2 + 1/W2

    const int sx_raw = shift[2 * n + 0];
    const int sy_raw = shift[2 * n + 1];
    // First staged (unclamped) source row; fp jitter can lower floor by 1,
    // so rows [T+sy-5 , T+sy+4] cover every y0/y1 of this tile.
    const int S0 = T + sy_raw - 5;

    // --- per-thread x params (column j), registers ---
    float xw0, xw1;
    int   xc0, xc1;
    {
        float a     = start + (float)j * step;
        float g     = a + (float)sx_raw * scale;
        float coord = ((g + 1.0f) * (float)HP - 1.0f) * 0.5f;
        float f0    = floorf(coord);
        int   i0p   = (int)f0;              // padded-canvas coord
        float w1    = coord - f0;
        float w0    = 1.0f - w1;
        xw0 = (i0p >= 0     && i0p     <= HP - 1) ? w0 : 0.0f;
        xw1 = (i0p + 1 >= 0 && i0p + 1 <= HP - 1) ? w1 : 0.0f;
        xc0 = min(max(i0p     - PADV, 0), W_IMG - 1);
        xc1 = min(max(i0p + 1 - PADV, 0), W_IMG - 1);
    }

    // --- y params for the 8 output rows ---
    if (j < ROWS_PB) {
        int   i     = T + j;
        float a     = start + (float)i * step;
        float g     = a + (float)sy_raw * scale;
        float coord = ((g + 1.0f) * (float)HP - 1.0f) * 0.5f;
        float f0    = floorf(coord);
        int   i0p   = (int)f0;
        float w1    = coord - f0;
        float w0    = 1.0f - w1;
        s_yw0[j]  = (i0p >= 0     && i0p     <= HP - 1) ? w0 : 0.0f;
        s_yw1[j]  = (i0p + 1 >= 0 && i0p + 1 <= HP - 1) ? w1 : 0.0f;
        s_yidx[j] = (i0p - PADV) - S0;      // in [0, 8]; +1 gives y1 row
    }

    // --- A1: stage 10 raw rows, aligned coalesced float4 loads ---
    const float* img = x + (size_t)(n * C_CH + c) * (H_IMG * W_IMG);
    #pragma unroll
    for (int t = 0; t < 3; ++t) {
        int idx = j + t * 224;              // 0..671; valid < 560
        if (idx < STAGE_F4) {
            int k  = idx / F4_PER_ROW;
            int q4 = idx % F4_PER_ROW;
            int src = min(max(S0 + k, 0), H_IMG - 1);   // y replicate-clamp
            float4 v = *(const float4*)(img + (size_t)src * W_IMG + 4 * q4);
            *(float4*)&s_raw[k * RAW_STRIDE + 4 * q4] = v;
        }
    }
    __syncthreads();

    // --- A2: x-blend from smem (conflict-free: consecutive lanes -> consecutive banks) ---
    #pragma unroll
    for (int k = 0; k < STAGE_ROWS; ++k) {
        float v = s_raw[k * RAW_STRIDE + xc0] * xw0
                + s_raw[k * RAW_STRIDE + xc1] * xw1;
        s_blend[k * BL_STRIDE + j] = v;
    }
    __syncthreads();

    // --- B: vector y-blend, float4 out ---
    float* outbase = out + (size_t)(n * C_CH + c) * (H_IMG * W_IMG);
    #pragma unroll
    for (int p = 0; p < 2; ++p) {
        int id = j + p * 224;               // 0..447
        int r  = id / F4_PER_ROW;           // 0..7
        int c4 = id % F4_PER_ROW;           // 0..55
        int   yi = s_yidx[r];
        float w0 = s_yw0[r];
        float w1 = s_yw1[r];
        const float4 a = *(const float4*)&s_blend[ yi      * BL_STRIDE + 4 * c4];
        const float4 b = *(const float4*)&s_blend[(yi + 1) * BL_STRIDE + 4 * c4];
        float4 o;
        o.x = a.x * w0 + b.x * w1;
        o.y = a.y * w0 + b.y * w1;
        o.z = a.z * w0 + b.z * w1;
        o.w = a.w * w0 + b.w * w1;
        *(float4*)&outbase[(size_t)(T + r) * W_IMG + 4 * c4] = o;
    }
}

extern "C" void kernel_launch(void* const* d_in, const int* in_sizes, int n_in,
                              void* d_out, int out_size) {
    const float* x     = (const float*)d_in[0];
    const int*   shift = (const int*)d_in[1];
    float*       out   = (float*)d_out;
    shift_aug_kernel<<<N_IMG * C_CH * TILES_PER_CH, 224>>>(x, shift, out);
}

// round 6
// speedup vs baseline: 1.4833x; 1.1164x over previous
#include <cuda_runtime.h>

// RandomShiftsAug: x (128,9,224,224) f32, shift (128,1,1,2) i32 in [0, 2*pad].
//
// Exact-math identity: the normalized grid unnormalizes to
//   coord_x(j) = j + shift_x,  coord_y(i) = i + shift_y   (exactly, since
//   (1/H2+1/W2)*H2/2 == 1 for H==W). Bilinear weights are therefore 0/1 up to
// fp32 rounding (~1e-5..1e-4), and the dominant corner round(coord) is always
// inside the padded canvas (weight kept). So the reference equals, to ~1e-5
// relative (gate is 1e-3):
//   out[n,c,i,j] = x[n,c, clamp(i+sy-4,0,223), clamp(j+sx-4,0,223)]
// -> a per-image integer shifted copy with replicate clamp. No smem, no sync.
//
// Interior float4: dx = 4*qlo + m; load two aligned float4 (A,B), select the
// m-rotated window (pure register selection inside uniform branches), store.
// Edge float4 columns (<=2 of 56) use a scalar clamped path.

#define N_IMG 128
#define C_CH  9
#define H_IMG 224
#define W_IMG 224
#define PADV  4
#define F4    (W_IMG / 4)          // 56 float4 per row
#define ROWS_PER_BLK 56
#define BLKS_PER_CH  (H_IMG / ROWS_PER_BLK)   // 4

__global__ __launch_bounds__(224) void nn_shift_kernel(
    const float* __restrict__ x,
    const int*   __restrict__ shift,
    float*       __restrict__ out)
{
    const int blk     = blockIdx.x;
    const int quarter = blk % BLKS_PER_CH;
    const int bc      = blk / BLKS_PER_CH;      // n*C + c
    const int n       = bc / C_CH;
    const int j       = threadIdx.x;            // 0..223
    const int q       = j % F4;                  // output float4 column
    const int rs      = quarter * ROWS_PER_BLK + (j / F4);  // start row, stride 4

    const int dx  = shift[2 * n + 0] - PADV;     // in [-4, 4]
    const int dy  = shift[2 * n + 1] - PADV;
    const int qlo = dx >> 2;                     // arithmetic shift: floor(dx/4)
    const int m   = dx & 3;                      // 0..3

    const size_t  base = (size_t)bc * (H_IMG * W_IMG);
    const float*  src  = x + base;
    const float4* src4 = (const float4*)src;
    float4*       dst4 = (float4*)(out + base);

    const int  aq   = q + qlo;                   // aligned source f4 index
    const bool edge = (aq < 0) || (((m != 0) ? (aq + 1) : aq) > F4 - 1);

    if (!edge) {
        if (m == 0) {
            #pragma unroll 7
            for (int t = 0; t < 14; ++t) {
                int r  = rs + t * 4;
                int sr = min(max(r + dy, 0), H_IMG - 1);
                dst4[r * F4 + q] = src4[sr * F4 + aq];
            }
        } else if (m == 1) {
            #pragma unroll 7
            for (int t = 0; t < 14; ++t) {
                int r  = rs + t * 4;
                int sr = min(max(r + dy, 0), H_IMG - 1);
                float4 A = src4[sr * F4 + aq];
                float4 B = src4[sr * F4 + aq + 1];
                dst4[r * F4 + q] = make_float4(A.y, A.z, A.w, B.x);
            }
        } else if (m == 2) {
            #pragma unroll 7
            for (int t = 0; t < 14; ++t) {
                int r  = rs + t * 4;
                int sr = min(max(r + dy, 0), H_IMG - 1);
                float4 A = src4[sr * F4 + aq];
                float4 B = src4[sr * F4 + aq + 1];
                dst4[r * F4 + q] = make_float4(A.z, A.w, B.x, B.y);
            }
        } else {
            #pragma unroll 7
            for (int t = 0; t < 14; ++t) {
                int r  = rs + t * 4;
                int sr = min(max(r + dy, 0), H_IMG - 1);
                float4 A = src4[sr * F4 + aq];
                float4 B = src4[sr * F4 + aq + 1];
                dst4[r * F4 + q] = make_float4(A.w, B.x, B.y, B.z);
            }
        }
    } else {
        const int c0 = min(max(4 * q + 0 + dx, 0), W_IMG - 1);
        const int c1 = min(max(4 * q + 1 + dx, 0), W_IMG - 1);
        const int c2 = min(max(4 * q + 2 + dx, 0), W_IMG - 1);
        const int c3 = min(max(4 * q + 3 + dx, 0), W_IMG - 1);
        #pragma unroll 7
        for (int t = 0; t < 14; ++t) {
            int r  = rs + t * 4;
            int sr = min(max(r + dy, 0), H_IMG - 1);
            const float* row = src + (size_t)sr * W_IMG;
            float4 o;
            o.x = row[c0];
            o.y = row[c1];
            o.z = row[c2];
            o.w = row[c3];
            dst4[r * F4 + q] = o;
        }
    }
}

extern "C" void kernel_launch(void* const* d_in, const int* in_sizes, int n_in,
                              void* d_out, int out_size) {
    const float* x     = (const float*)d_in[0];
    const int*   shift = (const int*)d_in[1];
    float*       out   = (float*)d_out;
    nn_shift_kernel<<<N_IMG * C_CH * BLKS_PER_CH, 224>>>(x, shift, out);
}

// round 7
// speedup vs baseline: 1.5624x; 1.0533x over previous
#include <cuda_runtime.h>

// RandomShiftsAug == per-image integer shifted copy with replicate clamp:
//   out[n,c,i,j] = x[n,c, clamp(i+sy-4), clamp(j+sx-4)]
// (exact-math identity of the reference's grid_sample; bilinear weights are
//  0/1 up to fp32 rounding ~1e-5, gate is 1e-3).
//
// Interior: dx = 4*qlo + m; two aligned LDG.128 (A,B) + register select + STG.128.
// Software-pipelined (prefetch depth 2) for MLP; streaming stores (__stcs).

#define N_IMG 128
#define C_CH  9
#define H_IMG 224
#define W_IMG 224
#define PADV  4
#define F4    (W_IMG / 4)                    // 56 float4 per row
#define ROWS_PER_BLK 28
#define BLKS_PER_CH  (H_IMG / ROWS_PER_BLK)  // 8
#define ITERS (ROWS_PER_BLK / 4)             // 7

__global__ __launch_bounds__(224) void nn_shift_kernel(
    const float* __restrict__ x,
    const int*   __restrict__ shift,
    float*       __restrict__ out)
{
    const int blk   = blockIdx.x;
    const int part  = blk % BLKS_PER_CH;
    const int bc    = blk / BLKS_PER_CH;        // n*C + c
    const int n     = bc / C_CH;
    const int j     = threadIdx.x;              // 0..223
    const int q     = j % F4;                   // output float4 column
    const int rs    = part * ROWS_PER_BLK + (j / F4);  // start row, stride 4

    const int dx  = shift[2 * n + 0] - PADV;    // [-4, 4]
    const int dy  = shift[2 * n + 1] - PADV;
    const int qlo = dx >> 2;                    // floor(dx/4)
    const int m   = dx & 3;

    const size_t  base = (size_t)bc * (H_IMG * W_IMG);
    const float*  src  = x + base;
    const float4* src4 = (const float4*)src;
    float4*       dst4 = (float4*)(out + base);

    const int  aq   = q + qlo;
    const bool edge = (aq < 0) || (((m != 0) ? (aq + 1) : aq) > F4 - 1);

    if (!edge) {
        // helper: clamped source row index for output row r
        #define SRCROW(r) (min(max((r) + dy, 0), H_IMG - 1))
        if (m == 0) {
            float4 A = src4[SRCROW(rs) * F4 + aq];
            #pragma unroll
            for (int t = 0; t < ITERS; ++t) {
                int r = rs + t * 4;
                float4 An;
                if (t + 1 < ITERS) An = src4[SRCROW(r + 4) * F4 + aq];
                __stcs(&dst4[r * F4 + q], A);
                A = An;
            }
        } else if (m == 1) {
            int sr0 = SRCROW(rs) * F4 + aq;
            float4 A = src4[sr0], B = src4[sr0 + 1];
            #pragma unroll
            for (int t = 0; t < ITERS; ++t) {
                int r = rs + t * 4;
                float4 An, Bn;
                if (t + 1 < ITERS) {
                    int srn = SRCROW(r + 4) * F4 + aq;
                    An = src4[srn]; Bn = src4[srn + 1];
                }
                __stcs(&dst4[r * F4 + q], make_float4(A.y, A.z, A.w, B.x));
                A = An; B = Bn;
            }
        } else if (m == 2) {
            int sr0 = SRCROW(rs) * F4 + aq;
            float4 A = src4[sr0], B = src4[sr0 + 1];
            #pragma unroll
            for (int t = 0; t < ITERS; ++t) {
                int r = rs + t * 4;
                float4 An, Bn;
                if (t + 1 < ITERS) {
                    int srn = SRCROW(r + 4) * F4 + aq;
                    An = src4[srn]; Bn = src4[srn + 1];
                }
                __stcs(&dst4[r * F4 + q], make_float4(A.z, A.w, B.x, B.y));
                A = An; B = Bn;
            }
        } else {
            int sr0 = SRCROW(rs) * F4 + aq;
            float4 A = src4[sr0], B = src4[sr0 + 1];
            #pragma unroll
            for (int t = 0; t < ITERS; ++t) {
                int r = rs + t * 4;
                float4 An, Bn;
                if (t + 1 < ITERS) {
                    int srn = SRCROW(r + 4) * F4 + aq;
                    An = src4[srn]; Bn = src4[srn + 1];
                }
                __stcs(&dst4[r * F4 + q], make_float4(A.w, B.x, B.y, B.z));
                A = An; B = Bn;
            }
        }
        #undef SRCROW
    } else {
        const int c0 = min(max(4 * q + 0 + dx, 0), W_IMG - 1);
        const int c1 = min(max(4 * q + 1 + dx, 0), W_IMG - 1);
        const int c2 = min(max(4 * q + 2 + dx, 0), W_IMG - 1);
        const int c3 = min(max(4 * q + 3 + dx, 0), W_IMG - 1);
        #pragma unroll
        for (int t = 0; t < ITERS; ++t) {
            int r  = rs + t * 4;
            int sr = min(max(r + dy, 0), H_IMG - 1);
            const float* row = src + (size_t)sr * W_IMG;
            float4 o;
            o.x = row[c0];
            o.y = row[c1];
            o.z = row[c2];
            o.w = row[c3];
            __stcs(&dst4[r * F4 + q], o);
        }
    }
}

extern "C" void kernel_launch(void* const* d_in, const int* in_sizes, int n_in,
                              void* d_out, int out_size) {
    const float* x     = (const float*)d_in[0];
    const int*   shift = (const int*)d_in[1];
    float*       out   = (float*)d_out;
    nn_shift_kernel<<<N_IMG * C_CH * BLKS_PER_CH, 224>>>(x, shift, out);
}